// round 1
// baseline (speedup 1.0000x reference)
#include <cuda_runtime.h>
#include <cstdint>

// -----------------------------------------------------------------------------
// Surv_Loss:
//   status==1 : -log(y_pred[i, y[i]])
//   status==0 : -log(1 - sum_{j<y[i]} y_pred[i, j])
//   output    : scalar sum over all B rows (fp32)
//
// Strategy: one warp per row. status is row-uniform -> no intra-warp divergence.
//   - status==0: lane-strided contiguous read of y[i] floats (coalesced 128B),
//     warp shuffle reduction.
//   - status==1: single 4B gather by lane 0.
// Per-block partial sums go to a static __device__ double array (no atomics,
// no init required, deterministic, graph-capturable). A second tiny kernel
// reduces the partials in double and writes the fp32 scalar.
// -----------------------------------------------------------------------------

#define BLOCK_THREADS 256
#define WARPS_PER_BLOCK (BLOCK_THREADS / 32)
#define MAX_PARTIALS 65536

__device__ double g_partials[MAX_PARTIALS];

__global__ void __launch_bounds__(BLOCK_THREADS)
surv_loss_main(const float* __restrict__ y_pred,
               const int* __restrict__ y,
               const int* __restrict__ status,
               int B, int T)
{
    const int warp_in_block = threadIdx.x >> 5;
    const int lane          = threadIdx.x & 31;
    const int row           = blockIdx.x * WARPS_PER_BLOCK + warp_in_block;

    __shared__ float warp_vals[WARPS_PER_BLOCK];

    float val = 0.0f;

    if (row < B) {
        const int yv = __ldg(&y[row]);       // broadcast within warp (same addr)
        const int st = __ldg(&status[row]);
        const float* rp = y_pred + (size_t)row * (size_t)T;

        if (st == 1) {
            if (lane == 0) {
                val = -logf(__ldg(&rp[yv]));
            }
        } else {
            // exclusive prefix sum of rp[0 .. yv-1], lane-strided (coalesced)
            float acc = 0.0f;
            for (int j = lane; j < yv; j += 32) {
                acc += __ldg(&rp[j]);
            }
            #pragma unroll
            for (int o = 16; o > 0; o >>= 1)
                acc += __shfl_xor_sync(0xFFFFFFFFu, acc, o);
            if (lane == 0) {
                val = -logf(1.0f - acc);
            }
        }
    }

    if (lane == 0) warp_vals[warp_in_block] = val;
    __syncthreads();

    if (threadIdx.x == 0) {
        float s = 0.0f;
        #pragma unroll
        for (int w = 0; w < WARPS_PER_BLOCK; ++w) s += warp_vals[w];
        g_partials[blockIdx.x] = (double)s;
    }
}

__global__ void __launch_bounds__(1024)
surv_loss_reduce(float* __restrict__ out, int nblocks)
{
    __shared__ double sh[1024];
    double s = 0.0;
    for (int i = threadIdx.x; i < nblocks; i += 1024)
        s += g_partials[i];
    sh[threadIdx.x] = s;
    __syncthreads();
    #pragma unroll
    for (int o = 512; o > 0; o >>= 1) {
        if (threadIdx.x < o) sh[threadIdx.x] += sh[threadIdx.x + o];
        __syncthreads();
    }
    if (threadIdx.x == 0) out[0] = (float)sh[0];
}

extern "C" void kernel_launch(void* const* d_in, const int* in_sizes, int n_in,
                              void* d_out, int out_size)
{
    const float* y_pred = (const float*)d_in[0];
    const int*   y      = (const int*)d_in[1];
    const int*   status = (const int*)d_in[2];
    float*       out    = (float*)d_out;

    const int B = in_sizes[1];
    const int T = in_sizes[0] / B;

    int nblocks = (B + WARPS_PER_BLOCK - 1) / WARPS_PER_BLOCK;
    if (nblocks > MAX_PARTIALS) nblocks = MAX_PARTIALS;  // B=262144 -> 32768, safe

    surv_loss_main<<<nblocks, BLOCK_THREADS>>>(y_pred, y, status, B, T);
    surv_loss_reduce<<<1, 1024>>>(out, nblocks);
}

// round 2
// speedup vs baseline: 1.5500x; 1.5500x over previous
#include <cuda_runtime.h>
#include <cstdint>

// -----------------------------------------------------------------------------
// Surv_Loss (R2): one warp per row, grid-stride over rows.
//   status==1 : -log(y_pred[i, y[i]])          (single 4B gather)
//   status==0 : -log(1 - sum_{j<y[i]} y_pred)  (float4-vectorized prefix read)
// 2048 block partials (double) -> tiny reduce kernel.
// -----------------------------------------------------------------------------

#define BLOCK_THREADS 256
#define WARPS_PER_BLOCK (BLOCK_THREADS / 32)
#define NBLOCKS 2048
#define MAX_PARTIALS 4096

__device__ double g_partials[MAX_PARTIALS];

__global__ void __launch_bounds__(BLOCK_THREADS)
surv_loss_main(const float* __restrict__ y_pred,
               const int* __restrict__ y,
               const int* __restrict__ status,
               int B, int T)
{
    const int warp_in_block = threadIdx.x >> 5;
    const int lane          = threadIdx.x & 31;
    const int gwarp         = blockIdx.x * WARPS_PER_BLOCK + warp_in_block;
    const int total_warps   = gridDim.x * WARPS_PER_BLOCK;

    float wsum = 0.0f;   // per-lane accumulator across this warp's rows

    for (int row = gwarp; row < B; row += total_warps) {
        const int yv = __ldg(&y[row]);      // warp-broadcast load
        const int st = __ldg(&status[row]);
        const float* rp = y_pred + (size_t)row * (size_t)T;

        if (st == 1) {
            if (lane == 0)
                wsum += -logf(__ldg(&rp[yv]));
        } else {
            // exclusive prefix sum of rp[0 .. yv-1], float4 vectorized
            const float4* rp4 = (const float4*)rp;   // rows are 2KB-aligned
            const int nf   = yv >> 2;                // full float4 chunks
            const int rem  = yv & 3;

            float acc = 0.0f;
            #pragma unroll 4
            for (int j = lane; j < nf; j += 32) {
                float4 v = __ldg(&rp4[j]);
                acc += (v.x + v.y) + (v.z + v.w);
            }
            if (lane < rem)
                acc += __ldg(&rp[(nf << 2) + lane]);

            #pragma unroll
            for (int o = 16; o > 0; o >>= 1)
                acc += __shfl_xor_sync(0xFFFFFFFFu, acc, o);

            if (lane == 0)
                wsum += -logf(1.0f - acc);
        }
    }

    // block reduction: lane 0 of each warp -> shared -> double partial
    __shared__ float warp_vals[WARPS_PER_BLOCK];
    if (lane == 0) warp_vals[warp_in_block] = wsum;
    __syncthreads();

    if (threadIdx.x == 0) {
        double s = 0.0;
        #pragma unroll
        for (int w = 0; w < WARPS_PER_BLOCK; ++w) s += (double)warp_vals[w];
        g_partials[blockIdx.x] = s;
    }
}

__global__ void __launch_bounds__(1024)
surv_loss_reduce(float* __restrict__ out, int nblocks)
{
    __shared__ double sh[32];
    const int lane = threadIdx.x & 31;
    const int wid  = threadIdx.x >> 5;

    double s = 0.0;
    for (int i = threadIdx.x; i < nblocks; i += 1024)
        s += g_partials[i];

    // warp reduce (double via shuffles of hi/lo not needed: use __shfl_down_sync on double)
    #pragma unroll
    for (int o = 16; o > 0; o >>= 1)
        s += __shfl_down_sync(0xFFFFFFFFu, s, o);

    if (lane == 0) sh[wid] = s;
    __syncthreads();

    if (wid == 0) {
        double t = (lane < 32) ? sh[lane] : 0.0;
        #pragma unroll
        for (int o = 16; o > 0; o >>= 1)
            t += __shfl_down_sync(0xFFFFFFFFu, t, o);
        if (lane == 0) out[0] = (float)t;
    }
}

extern "C" void kernel_launch(void* const* d_in, const int* in_sizes, int n_in,
                              void* d_out, int out_size)
{
    const float* y_pred = (const float*)d_in[0];
    const int*   y      = (const int*)d_in[1];
    const int*   status = (const int*)d_in[2];
    float*       out    = (float*)d_out;

    const int B = in_sizes[1];
    const int T = in_sizes[0] / B;

    surv_loss_main<<<NBLOCKS, BLOCK_THREADS>>>(y_pred, y, status, B, T);
    surv_loss_reduce<<<1, 1024>>>(out, NBLOCKS);
}

// round 3
// speedup vs baseline: 1.9315x; 1.2461x over previous
#include <cuda_runtime.h>
#include <cstdint>

// -----------------------------------------------------------------------------
// Surv_Loss (R3): 32 rows per warp batch, single fused kernel.
//   - y/status loaded coalesced (one lane per row of the batch)
//   - status==1 rows: lane-parallel gather + logf (32-wide, no cooperation)
//   - status==0 rows: ballot-enumerated, processed in PAIRS with interleaved
//     float4 loads and a paired 6-shfl butterfly reduce (sums land on lanes 0/16)
//   - final reduction fused via threadfence-reduction last-block pattern
// -----------------------------------------------------------------------------

#define BLOCK_THREADS 256
#define WARPS_PER_BLOCK 8
#define NBLOCKS 1024
#define MAX_PARTIALS 2048
#define FULL 0xFFFFFFFFu

__device__ double g_partials[MAX_PARTIALS];
__device__ unsigned int g_count = 0;

__global__ void __launch_bounds__(BLOCK_THREADS)
surv_loss_kernel(const float* __restrict__ y_pred,
                 const int* __restrict__ y,
                 const int* __restrict__ status,
                 float* __restrict__ out,
                 int B, int T)
{
    const int lane  = threadIdx.x & 31;
    const int wib   = threadIdx.x >> 5;
    const int gwarp = blockIdx.x * WARPS_PER_BLOCK + wib;
    const int nwarps = gridDim.x * WARPS_PER_BLOCK;

    float wsum = 0.0f;   // per-lane accumulator

    for (int base = gwarp * 32; base < B; base += nwarps * 32) {
        const int  row   = base + lane;
        const bool valid = row < B;
        const int  my_y  = valid ? __ldg(&y[row]) : 0;
        const int  my_st = valid ? __ldg(&status[row]) : 1;

        // --- status==1 rows: fully lane-parallel gather ---
        if (valid && my_st == 1) {
            wsum += -logf(__ldg(y_pred + (size_t)row * (size_t)T + my_y));
        }
        // (status==0 with y==0 contributes -log(1-0)=0; excluded below)

        // --- status==0 rows: warp-cooperative, two at a time ---
        unsigned m = __ballot_sync(FULL, valid && my_st == 0 && my_y > 0);
        while (m) {
            const int l0 = __ffs(m) - 1; m &= m - 1;
            int l1 = -1;
            if (m) { l1 = __ffs(m) - 1; m &= m - 1; }

            const int yv0 = __shfl_sync(FULL, my_y, l0);
            const int yv1s = __shfl_sync(FULL, my_y, (l1 >= 0) ? l1 : l0);
            const int yv1 = (l1 >= 0) ? yv1s : 0;

            const float* r0p = y_pred + (size_t)(base + l0) * (size_t)T;
            const float* r1p = y_pred + (size_t)(base + ((l1 >= 0) ? l1 : l0)) * (size_t)T;

            float acc0 = 0.0f, acc1 = 0.0f;

            if ((T & 3) == 0) {
                // vector path (rows 16B-aligned when T%4==0)
                const float4* p0 = (const float4*)r0p;
                const float4* p1 = (const float4*)r1p;
                const int nf0 = yv0 >> 2;
                const int nf1 = yv1 >> 2;
                const int nmax = nf0 > nf1 ? nf0 : nf1;
                for (int j = lane; j < nmax; j += 32) {
                    if (j < nf0) { float4 v = __ldg(&p0[j]); acc0 += (v.x + v.y) + (v.z + v.w); }
                    if (j < nf1) { float4 v = __ldg(&p1[j]); acc1 += (v.x + v.y) + (v.z + v.w); }
                }
                if (lane < (yv0 & 3)) acc0 += __ldg(r0p + (nf0 << 2) + lane);
                if (lane < (yv1 & 3)) acc1 += __ldg(r1p + (nf1 << 2) + lane);
            } else {
                // scalar fallback (unused for T=512)
                for (int j = lane; j < yv0; j += 32) acc0 += __ldg(r0p + j);
                for (int j = lane; j < yv1; j += 32) acc1 += __ldg(r1p + j);
            }

            // paired butterfly reduce: lane 0 gets sum(acc0), lane 16 gets sum(acc1)
            const float ta = __shfl_xor_sync(FULL, acc0, 16);
            const float tb = __shfl_xor_sync(FULL, acc1, 16);
            float c = (lane < 16) ? (acc0 + ta) : (acc1 + tb);
            #pragma unroll
            for (int o = 8; o > 0; o >>= 1)
                c += __shfl_xor_sync(FULL, c, o);

            if (lane == 0)               wsum += -logf(1.0f - c);
            if (lane == 16 && l1 >= 0)   wsum += -logf(1.0f - c);
        }
    }

    // --- warp reduce of per-lane wsum ---
    #pragma unroll
    for (int o = 16; o > 0; o >>= 1)
        wsum += __shfl_xor_sync(FULL, wsum, o);

    __shared__ float  warp_vals[WARPS_PER_BLOCK];
    __shared__ bool   is_last;
    if (lane == 0) warp_vals[wib] = wsum;
    __syncthreads();

    if (threadIdx.x == 0) {
        double s = 0.0;
        #pragma unroll
        for (int w = 0; w < WARPS_PER_BLOCK; ++w) s += (double)warp_vals[w];
        g_partials[blockIdx.x] = s;
        __threadfence();
        unsigned done = atomicAdd(&g_count, 1u);
        is_last = (done == gridDim.x - 1);
    }
    __syncthreads();

    // --- last block reduces all partials (deterministic fixed-order tree) ---
    if (is_last) {
        volatile double* gp = g_partials;   // bypass L1 (other SMs wrote these)
        double s = 0.0;
        for (int i = threadIdx.x; i < (int)gridDim.x; i += BLOCK_THREADS)
            s += gp[i];

        #pragma unroll
        for (int o = 16; o > 0; o >>= 1)
            s += __shfl_down_sync(FULL, s, o);

        __shared__ double sh[WARPS_PER_BLOCK];
        if (lane == 0) sh[wib] = s;
        __syncthreads();

        if (threadIdx.x == 0) {
            double t = 0.0;
            #pragma unroll
            for (int w = 0; w < WARPS_PER_BLOCK; ++w) t += sh[w];
            out[0] = (float)t;
            atomicExch(&g_count, 0u);   // reset for next graph replay
        }
    }
}

extern "C" void kernel_launch(void* const* d_in, const int* in_sizes, int n_in,
                              void* d_out, int out_size)
{
    const float* y_pred = (const float*)d_in[0];
    const int*   y      = (const int*)d_in[1];
    const int*   status = (const int*)d_in[2];
    float*       out    = (float*)d_out;

    const int B = in_sizes[1];
    const int T = in_sizes[0] / B;

    surv_loss_kernel<<<NBLOCKS, BLOCK_THREADS>>>(y_pred, y, status, out, B, T);
}

// round 4
// speedup vs baseline: 2.7496x; 1.4236x over previous
#include <cuda_runtime.h>
#include <cstdint>

// -----------------------------------------------------------------------------
// Surv_Loss (R4): 32 rows per warp batch, QUAD-interleaved prefix sums.
//   - y/status loaded coalesced (one lane per row of the batch)
//   - status==1 rows: lane-parallel gather (issued BEFORE quad loop, consumed after)
//   - status==0 rows: ballot-enumerated, 4 rows per round; fully unrolled
//     predicated float4 load wave (<=16 LDG.128 + 4 LDG.32 in flight), then one
//     11-shfl quad reduce delivering 4 row sums at lanes 0/8/16/24.
//   - fused final reduction (threadfence last-block pattern, double accum)
// -----------------------------------------------------------------------------

#define BLOCK_THREADS 256
#define WARPS_PER_BLOCK 8
#define NBLOCKS 1024
#define MAX_PARTIALS 2048
#define FULL 0xFFFFFFFFu

__device__ double g_partials[MAX_PARTIALS];
__device__ unsigned int g_count = 0;

__global__ void __launch_bounds__(BLOCK_THREADS)
surv_loss_kernel(const float* __restrict__ y_pred,
                 const int* __restrict__ y,
                 const int* __restrict__ status,
                 float* __restrict__ out,
                 int B, int T)
{
    const int lane  = threadIdx.x & 31;
    const int wib   = threadIdx.x >> 5;
    const int gwarp = blockIdx.x * WARPS_PER_BLOCK + wib;
    const int nwarps = gridDim.x * WARPS_PER_BLOCK;

    float wsum = 0.0f;   // per-lane accumulator

    for (int base = gwarp * 32; base < B; base += nwarps * 32) {
        const int  row   = base + lane;
        const bool valid = row < B;
        const int  my_y  = valid ? __ldg(&y[row]) : 0;
        const int  my_st = valid ? __ldg(&status[row]) : 1;

        // --- status==1 rows: issue gather early, consume after the quad loop ---
        const bool has_g = valid && (my_st == 1);
        float gval = 1.0f;
        if (has_g) gval = __ldg(y_pred + (size_t)row * (size_t)T + my_y);

        // --- status==0 rows (y>0): 4 rows per round ---
        unsigned m = __ballot_sync(FULL, valid && my_st == 0 && my_y > 0);
        while (m) {
            int l0 = __ffs(m) - 1; m &= m - 1;
            int l1 = 32, l2 = 32, l3 = 32;
            if (m) { l1 = __ffs(m) - 1; m &= m - 1; }
            if (m) { l2 = __ffs(m) - 1; m &= m - 1; }
            if (m) { l3 = __ffs(m) - 1; m &= m - 1; }
            const int n = 1 + (l1 < 32) + (l2 < 32) + (l3 < 32);

            int yv0 = __shfl_sync(FULL, my_y, l0);
            int yv1 = __shfl_sync(FULL, my_y, l1 & 31); if (l1 == 32) yv1 = 0;
            int yv2 = __shfl_sync(FULL, my_y, l2 & 31); if (l2 == 32) yv2 = 0;
            int yv3 = __shfl_sync(FULL, my_y, l3 & 31); if (l3 == 32) yv3 = 0;

            const float* r0p = y_pred + (size_t)(base + (l0 & 31)) * (size_t)T;
            const float* r1p = y_pred + (size_t)(base + (l1 & 31)) * (size_t)T;
            const float* r2p = y_pred + (size_t)(base + (l2 & 31)) * (size_t)T;
            const float* r3p = y_pred + (size_t)(base + (l3 & 31)) * (size_t)T;

            const float4* p0 = (const float4*)r0p;
            const float4* p1 = (const float4*)r1p;
            const float4* p2 = (const float4*)r2p;
            const float4* p3 = (const float4*)r3p;

            const int nf0 = yv0 >> 2, nf1 = yv1 >> 2, nf2 = yv2 >> 2, nf3 = yv3 >> 2;

            float a0 = 0.0f, a1 = 0.0f, a2 = 0.0f, a3 = 0.0f;

            // full unrolled predicated load wave: y < 512 -> nf <= 128 -> 4 iters
            #pragma unroll
            for (int u = 0; u < 4; ++u) {
                const int j = lane + u * 32;
                if (j < nf0) { float4 v = __ldg(&p0[j]); a0 += (v.x + v.y) + (v.z + v.w); }
                if (j < nf1) { float4 v = __ldg(&p1[j]); a1 += (v.x + v.y) + (v.z + v.w); }
                if (j < nf2) { float4 v = __ldg(&p2[j]); a2 += (v.x + v.y) + (v.z + v.w); }
                if (j < nf3) { float4 v = __ldg(&p3[j]); a3 += (v.x + v.y) + (v.z + v.w); }
            }
            // remainders (0..3 scalars per row), same wave
            if (lane < (yv0 & 3)) a0 += __ldg(r0p + (nf0 << 2) + lane);
            if (lane < (yv1 & 3)) a1 += __ldg(r1p + (nf1 << 2) + lane);
            if (lane < (yv2 & 3)) a2 += __ldg(r2p + (nf2 << 2) + lane);
            if (lane < (yv3 & 3)) a3 += __ldg(r3p + (nf3 << 2) + lane);

            // quad reduce: fold 16 & 8 on all four accs -> partials over lanes
            // sharing (lane&7); select acc by 8-lane group; fold 4,2,1.
            a0 += __shfl_xor_sync(FULL, a0, 16);
            a1 += __shfl_xor_sync(FULL, a1, 16);
            a2 += __shfl_xor_sync(FULL, a2, 16);
            a3 += __shfl_xor_sync(FULL, a3, 16);
            a0 += __shfl_xor_sync(FULL, a0, 8);
            a1 += __shfl_xor_sync(FULL, a1, 8);
            a2 += __shfl_xor_sync(FULL, a2, 8);
            a3 += __shfl_xor_sync(FULL, a3, 8);

            float c = (lane & 16) ? ((lane & 8) ? a3 : a2)
                                  : ((lane & 8) ? a1 : a0);
            c += __shfl_xor_sync(FULL, c, 4);
            c += __shfl_xor_sync(FULL, c, 2);
            c += __shfl_xor_sync(FULL, c, 1);
            // c now holds, replicated in each 8-lane group g, the full sum of acc_g

            if ((lane & 7) == 0 && (lane >> 3) < n)
                wsum += -__logf(1.0f - c);
        }

        if (has_g) wsum += -__logf(gval);
    }

    // --- warp reduce of per-lane wsum ---
    #pragma unroll
    for (int o = 16; o > 0; o >>= 1)
        wsum += __shfl_xor_sync(FULL, wsum, o);

    __shared__ float warp_vals[WARPS_PER_BLOCK];
    __shared__ bool  is_last;
    if (lane == 0) warp_vals[wib] = wsum;
    __syncthreads();

    if (threadIdx.x == 0) {
        double s = 0.0;
        #pragma unroll
        for (int w = 0; w < WARPS_PER_BLOCK; ++w) s += (double)warp_vals[w];
        g_partials[blockIdx.x] = s;
        __threadfence();
        unsigned done = atomicAdd(&g_count, 1u);
        is_last = (done == gridDim.x - 1);
    }
    __syncthreads();

    // --- last block reduces all partials (deterministic fixed order) ---
    if (is_last) {
        volatile double* gp = g_partials;
        double s = 0.0;
        for (int i = threadIdx.x; i < (int)gridDim.x; i += BLOCK_THREADS)
            s += gp[i];

        #pragma unroll
        for (int o = 16; o > 0; o >>= 1)
            s += __shfl_down_sync(FULL, s, o);

        __shared__ double sh[WARPS_PER_BLOCK];
        if (lane == 0) sh[wib] = s;
        __syncthreads();

        if (threadIdx.x == 0) {
            double t = 0.0;
            #pragma unroll
            for (int w = 0; w < WARPS_PER_BLOCK; ++w) t += sh[w];
            out[0] = (float)t;
            atomicExch(&g_count, 0u);   // reset for next graph replay
        }
    }
}

extern "C" void kernel_launch(void* const* d_in, const int* in_sizes, int n_in,
                              void* d_out, int out_size)
{
    const float* y_pred = (const float*)d_in[0];
    const int*   y      = (const int*)d_in[1];
    const int*   status = (const int*)d_in[2];
    float*       out    = (float*)d_out;

    const int B = in_sizes[1];
    const int T = in_sizes[0] / B;

    surv_loss_kernel<<<NBLOCKS, BLOCK_THREADS>>>(y_pred, y, status, out, B, T);
}